// round 2
// baseline (speedup 1.0000x reference)
#include <cuda_runtime.h>
#include <cstdint>

// out = x + exp(0.5*(relu(x@W1+b1)@W2 + b2)) * eps
// Shapes: x,eps,out [B,256]; W1 [256,64]; b1 [64]; W2 [64,256]; b2 [256]
// B = 131072 (assumed divisible by 128)

#define SDIM 256
#define HDIM 64
#define TILE_ROWS 128
#define SX_STRIDE 260   // 128*260 floats, bank(addr)=(4r+k)%32
#define SH_STRIDE 68    // bank(addr)=(4r+k)%32

// dynamic smem layout (floats):
//   [0, 128*260)              : sX  (phase A)   / sH [128*68] (phase B, aliased)
//   [128*260, +16384)         : sW1 (phase A)   / sW2 (phase B, aliased)
//   [.., +64)                 : sb1
//   [.., +256)                : sb2
#define SMEM_W_OFF   (TILE_ROWS * SX_STRIDE)
#define SMEM_B1_OFF  (SMEM_W_OFF + SDIM * HDIM)
#define SMEM_B2_OFF  (SMEM_B1_OFF + HDIM)
#define SMEM_FLOATS  (SMEM_B2_OFF + SDIM)
#define SMEM_BYTES   (SMEM_FLOATS * 4)

__global__ void __launch_bounds__(256, 1) mvn_fused_kernel(
    const float* __restrict__ x,
    const float* __restrict__ eps,
    const float* __restrict__ W1,
    const float* __restrict__ b1,
    const float* __restrict__ W2,
    const float* __restrict__ b2,
    float* __restrict__ out)
{
    extern __shared__ float smem[];
    float* sX  = smem;
    float* sW1 = smem + SMEM_W_OFF;
    float* sH  = smem;              // aliases sX after phase A
    float* sW2 = smem + SMEM_W_OFF; // aliases sW1 after phase A
    float* sb1 = smem + SMEM_B1_OFF;
    float* sb2 = smem + SMEM_B2_OFF;

    const int tid = threadIdx.x;
    const int cg  = tid & 15;   // colgroup: 4 consecutive cols
    const int rg  = tid >> 4;   // rowgroup: rows rg + 16*i, i in [0,8)

    const long long rowBase = (long long)blockIdx.x * TILE_ROWS;
    const float* xTile = x + rowBase * SDIM;

    // ---- cooperative loads: X tile, W1, b1, b2 ----
    {
        // X tile: 128*256 floats = 8192 float4
        const float4* src = reinterpret_cast<const float4*>(xTile);
        #pragma unroll
        for (int p = 0; p < 32; p++) {
            int f = tid + 256 * p;          // float4 index
            int r  = f >> 6;                // row
            int kk = f & 63;                // float4 within row
            float4 v = src[f];
            *reinterpret_cast<float4*>(&sX[r * SX_STRIDE + 4 * kk]) = v;
        }
        // W1: 16384 floats = 4096 float4 (dense [256][64])
        const float4* w1s = reinterpret_cast<const float4*>(W1);
        float4* w1d = reinterpret_cast<float4*>(sW1);
        #pragma unroll
        for (int p = 0; p < 16; p++) w1d[tid + 256 * p] = w1s[tid + 256 * p];
        if (tid < 16)
            reinterpret_cast<float4*>(sb1)[tid] = reinterpret_cast<const float4*>(b1)[tid];
        if (tid < 64)
            reinterpret_cast<float4*>(sb2)[tid] = reinterpret_cast<const float4*>(b2)[tid];
    }
    __syncthreads();

    // ---- Phase A: H = relu(X @ W1 + b1), thread computes 8 rows x 4 cols ----
    float acc[8][4];
    #pragma unroll
    for (int i = 0; i < 8; i++)
        #pragma unroll
        for (int j = 0; j < 4; j++) acc[i][j] = 0.0f;

    #pragma unroll 2
    for (int k = 0; k < SDIM; k++) {
        float4 b = *reinterpret_cast<const float4*>(&sW1[k * HDIM + 4 * cg]);
        float a[8];
        #pragma unroll
        for (int i = 0; i < 8; i++) a[i] = sX[(rg + 16 * i) * SX_STRIDE + k];
        #pragma unroll
        for (int i = 0; i < 8; i++) {
            acc[i][0] += a[i] * b.x;
            acc[i][1] += a[i] * b.y;
            acc[i][2] += a[i] * b.z;
            acc[i][3] += a[i] * b.w;
        }
    }

    float4 bb1 = *reinterpret_cast<const float4*>(&sb1[4 * cg]);

    __syncthreads();  // everyone done reading sX / sW1

    // write H (relu + bias) into sH; cooperatively load W2 into sW2
    #pragma unroll
    for (int i = 0; i < 8; i++) {
        float4 hv;
        hv.x = fmaxf(acc[i][0] + bb1.x, 0.0f);
        hv.y = fmaxf(acc[i][1] + bb1.y, 0.0f);
        hv.z = fmaxf(acc[i][2] + bb1.z, 0.0f);
        hv.w = fmaxf(acc[i][3] + bb1.w, 0.0f);
        *reinterpret_cast<float4*>(&sH[(rg + 16 * i) * SH_STRIDE + 4 * cg]) = hv;
    }
    {
        const float4* w2s = reinterpret_cast<const float4*>(W2);
        float4* w2d = reinterpret_cast<float4*>(sW2);
        #pragma unroll
        for (int p = 0; p < 16; p++) w2d[tid + 256 * p] = w2s[tid + 256 * p];
    }
    __syncthreads();

    // ---- Phase B: logits = H @ W2 + b2; out = x + exp(0.5*logit)*eps ----
    const float* epsTile = eps + rowBase * SDIM;
    float* outTile = out + rowBase * SDIM;

    #pragma unroll
    for (int c = 0; c < 4; c++) {
        float acc2[8][4];
        #pragma unroll
        for (int i = 0; i < 8; i++)
            #pragma unroll
            for (int j = 0; j < 4; j++) acc2[i][j] = 0.0f;

        #pragma unroll 2
        for (int k = 0; k < HDIM; k++) {
            float4 b = *reinterpret_cast<const float4*>(&sW2[k * SDIM + c * 64 + 4 * cg]);
            float a[8];
            #pragma unroll
            for (int i = 0; i < 8; i++) a[i] = sH[(rg + 16 * i) * SH_STRIDE + k];
            #pragma unroll
            for (int i = 0; i < 8; i++) {
                acc2[i][0] += a[i] * b.x;
                acc2[i][1] += a[i] * b.y;
                acc2[i][2] += a[i] * b.z;
                acc2[i][3] += a[i] * b.w;
            }
        }

        float4 bb2 = *reinterpret_cast<const float4*>(&sb2[c * 64 + 4 * cg]);

        #pragma unroll
        for (int i = 0; i < 8; i++) {
            int r = rg + 16 * i;
            long long idx = (long long)r * SDIM + c * 64 + 4 * cg;
            float4 xv = *reinterpret_cast<const float4*>(&xTile[idx]);
            float4 ev = *reinterpret_cast<const float4*>(&epsTile[idx]);
            float4 o;
            o.x = fmaf(__expf(0.5f * (acc2[i][0] + bb2.x)), ev.x, xv.x);
            o.y = fmaf(__expf(0.5f * (acc2[i][1] + bb2.y)), ev.y, xv.y);
            o.z = fmaf(__expf(0.5f * (acc2[i][2] + bb2.z)), ev.z, xv.z);
            o.w = fmaf(__expf(0.5f * (acc2[i][3] + bb2.w)), ev.w, xv.w);
            *reinterpret_cast<float4*>(&outTile[idx]) = o;
        }
    }
}

extern "C" void kernel_launch(void* const* d_in, const int* in_sizes, int n_in,
                              void* d_out, int out_size) {
    const float* x   = (const float*)d_in[0];
    const float* eps = (const float*)d_in[1];
    const float* W1  = (const float*)d_in[2];
    const float* b1  = (const float*)d_in[3];
    const float* W2  = (const float*)d_in[4];
    const float* b2  = (const float*)d_in[5];
    float* out = (float*)d_out;

    int B = in_sizes[0] / SDIM;
    int grid = B / TILE_ROWS;  // 1024 for B=131072

    static bool attr_set = false;  // idempotent attribute, deterministic work
    if (!attr_set) {
        cudaFuncSetAttribute(mvn_fused_kernel,
                             cudaFuncAttributeMaxDynamicSharedMemorySize, SMEM_BYTES);
        attr_set = true;
    }

    mvn_fused_kernel<<<grid, 256, SMEM_BYTES>>>(x, eps, W1, b1, W2, b2, out);
}

// round 4
// speedup vs baseline: 1.4663x; 1.4663x over previous
#include <cuda_runtime.h>
#include <cstdint>

// out = x + exp(0.5*(relu(x@W1+b1)@W2 + b2)) * eps
// x,eps,out [B,256] f32; W1 [256,64]; b1[64]; W2 [64,256]; b2[256]
// Persistent mma.sync (m16n8k8 tf32) kernel, 256 threads/CTA, 148 CTAs.

#define SDIM 256
#define HDIM 64
#define TMR  128

// smem float-index offsets
#define W1F 0          // W1 tf32, [k=256][64], XOR-swizzled       (64 KB)
#define W2F 16384      // W2 tf32, [k=64][256], XOR-swizzled       (64 KB)
#define XS0 32768      // X chunk slot0: 128 rows x 64 k, swizzled (32 KB)
#define XS1 40960      // slot1                                    (32 KB)
#define HS  49152      // H tf32: 128 x 64, swizzled               (32 KB)
#define B1S 57344      // 64 f32
#define B2S 57408      // 256 f32
#define SMEM_FLOATS 57664
#define SMEM_BYTES  (SMEM_FLOATS * 4)   // 230656 <= 232448 cap

__device__ __forceinline__ uint32_t to_tf32(float f) {
    uint32_t r; asm("cvt.rna.tf32.f32 %0, %1;" : "=r"(r) : "f"(f)); return r;
}
__device__ __forceinline__ float ex2f(float f) {
    float r; asm("ex2.approx.f32 %0, %1;" : "=f"(r) : "f"(f)); return r;
}
__device__ __forceinline__ void mma8(float* c,
    uint32_t a0, uint32_t a1, uint32_t a2, uint32_t a3, uint32_t b0, uint32_t b1) {
    asm volatile(
        "mma.sync.aligned.m16n8k8.row.col.f32.tf32.tf32.f32 "
        "{%0,%1,%2,%3},{%4,%5,%6,%7},{%8,%9},{%0,%1,%2,%3};"
        : "+f"(c[0]), "+f"(c[1]), "+f"(c[2]), "+f"(c[3])
        : "r"(a0), "r"(a1), "r"(a2), "r"(a3), "r"(b0), "r"(b1));
}

static __device__ __forceinline__ uint32_t smem_u32(const void* p) {
    uint32_t a;
    asm("{ .reg .u64 t; cvta.to.shared.u64 t, %1; cvt.u32.u64 %0, t; }" : "=r"(a) : "l"(p));
    return a;
}
#define CPA16(s, g)  asm volatile("cp.async.cg.shared.global [%0], [%1], 16;" :: "r"(s), "l"(g))
#define CPCOMMIT()   asm volatile("cp.async.commit_group;" ::: "memory")
#define CPWAIT1()    asm volatile("cp.async.wait_group 1;" ::: "memory")

// load one X chunk (128 rows x 64 floats) into a swizzled slot via cp.async
static __device__ __forceinline__ void load_chunk(
    const float* __restrict__ xT, int ck, float* slot) {
    const int tid = threadIdx.x;
    const float* gsrc = xT + ck * 64;
    #pragma unroll
    for (int j = 0; j < 8; j++) {
        int f = tid + 256 * j;
        int m = f >> 4, c4 = f & 15;
        uint32_t dst = smem_u32(slot + m * 64 + 4 * (c4 ^ (m & 7)));
        CPA16(dst, gsrc + m * SDIM + 4 * c4);
    }
}

__global__ void __launch_bounds__(256, 1) mvn_mma_kernel(
    const float* __restrict__ x, const float* __restrict__ eps,
    const float* __restrict__ W1, const float* __restrict__ b1,
    const float* __restrict__ W2, const float* __restrict__ b2,
    float* __restrict__ out, int numTiles)
{
    extern __shared__ float sm[];
    uint32_t* smu = reinterpret_cast<uint32_t*>(sm);

    const int tid  = threadIdx.x;
    const int w    = tid >> 5;
    const int lane = tid & 31;
    const int g    = lane >> 2;   // group (row within fragment, also B's n-offset)
    const int t4   = lane & 3;

    // ---- stage weights (tf32-converted, XOR-swizzled) + biases ----
    #pragma unroll 4
    for (int j = 0; j < 64; j++) {
        int idx = tid + 256 * j;
        int kk = idx >> 6, n = idx & 63;
        smu[W1F + kk * 64 + (n ^ (8 * (kk & 3)))] = to_tf32(W1[idx]);
    }
    #pragma unroll 4
    for (int j = 0; j < 64; j++) {
        int idx = tid + 256 * j;
        int kk = idx >> 8, n = idx & 255;
        smu[W2F + kk * 256 + (n ^ (8 * (kk & 3)))] = to_tf32(W2[idx]);
    }
    if (tid < 64) sm[B1S + tid] = b1[tid];
    sm[B2S + tid] = b2[tid];
    __syncthreads();

    const int G = gridDim.x;
    int t = blockIdx.x;

    // prefetch first tile's chunks 0,1
    load_chunk(x + (long long)t * TMR * SDIM, 0, sm + XS0); CPCOMMIT();
    load_chunk(x + (long long)t * TMR * SDIM, 1, sm + XS1); CPCOMMIT();

    const int arow = (16 * w + g) * 64 + t4;   // A-fragment base (X and H slots)

    for (; t < numTiles; t += G) {
        const long long base = (long long)t * TMR * SDIM;
        const float* xT = x + base;

        // ======== GEMM1: H = relu(X @ W1 + b1) ========
        float acc1[8][4];
        #pragma unroll
        for (int nt = 0; nt < 8; nt++)
            acc1[nt][0] = acc1[nt][1] = acc1[nt][2] = acc1[nt][3] = 0.0f;

        #pragma unroll
        for (int c = 0; c < 4; c++) {
            CPWAIT1();
            __syncthreads();
            const float* xs = sm + ((c & 1) ? XS1 : XS0);

            #pragma unroll
            for (int ks = 0; ks < 8; ks++) {
                int a0i = arow + 4 * ((2 * ks) ^ g);
                float f0 = xs[a0i], f1 = xs[a0i + 512];
                float f2 = xs[a0i ^ 4], f3 = xs[(a0i ^ 4) + 512];
                uint32_t A0 = to_tf32(f0), A1 = to_tf32(f1);
                uint32_t A2 = to_tf32(f2), A3 = to_tf32(f3);
                const uint32_t* bp = smu + W1F + (64 * c + 8 * ks + t4) * 64 + g;
                #pragma unroll
                for (int nt = 0; nt < 8; nt++) {
                    int o = 8 * (nt ^ t4);
                    mma8(acc1[nt], A0, A1, A2, A3, bp[o], bp[o + 256]);
                }
            }
            __syncthreads();   // all warps done with this slot

            int tn = t + G;
            if (c == 0)      { load_chunk(xT, 2, sm + XS0); }
            else if (c == 1) { load_chunk(xT, 3, sm + XS1); }
            else if (c == 2) { if (tn < numTiles) load_chunk(x + (long long)tn * TMR * SDIM, 0, sm + XS0); }
            else             { int tn2 = t + G; if (tn2 < numTiles) load_chunk(x + (long long)tn2 * TMR * SDIM, 1, sm + XS1); }
            CPCOMMIT();   // always commit (possibly empty group) to keep counts uniform
        }

        // ---- bias + relu + store H (tf32 bits) into swizzled smem ----
        {
            const int m0 = (16 * w + g) * 64;
            #pragma unroll
            for (int nt = 0; nt < 8; nt++) {
                int col = 8 * nt + 2 * t4;
                float2 bb = *reinterpret_cast<const float2*>(&sm[B1S + col]);
                uint2 p0, p1;
                p0.x = to_tf32(fmaxf(acc1[nt][0] + bb.x, 0.0f));
                p0.y = to_tf32(fmaxf(acc1[nt][1] + bb.y, 0.0f));
                p1.x = to_tf32(fmaxf(acc1[nt][2] + bb.x, 0.0f));
                p1.y = to_tf32(fmaxf(acc1[nt][3] + bb.y, 0.0f));
                int hi = HS + m0 + 4 * ((col >> 2) ^ g) + (col & 3);
                *reinterpret_cast<uint2*>(&smu[hi])       = p0;   // rows g
                *reinterpret_cast<uint2*>(&smu[hi + 512]) = p1;   // rows g+8
            }
        }
        __syncthreads();

        // ======== GEMM2 + fused epilogue, per 64-column chunk ========
        const float* eT = eps + base;
        float* oT = out + base;
        const int r0 = 16 * w + g;

        #pragma unroll
        for (int cc = 0; cc < 4; cc++) {
            float acc2[8][4];
            #pragma unroll
            for (int nt = 0; nt < 8; nt++)
                acc2[nt][0] = acc2[nt][1] = acc2[nt][2] = acc2[nt][3] = 0.0f;

            #pragma unroll
            for (int ks = 0; ks < 8; ks++) {
                int a0i = HS + arow + 4 * ((2 * ks) ^ g);
                uint32_t A0 = smu[a0i], A1 = smu[a0i + 512];
                uint32_t A2 = smu[a0i ^ 4], A3 = smu[(a0i ^ 4) + 512];
                const uint32_t* bp = smu + W2F + (8 * ks + t4) * 256 + 64 * cc + g;
                #pragma unroll
                for (int nt = 0; nt < 8; nt++) {
                    int o = 8 * (nt ^ t4);
                    mma8(acc2[nt], A0, A1, A2, A3, bp[o], bp[o + 1024]);
                }
            }

            // epilogue: out = x + exp2(0.72134752*(d + b2)) * eps
            #pragma unroll
            for (int nt = 0; nt < 8; nt++) {
                int col = 64 * cc + 8 * nt + 2 * t4;
                float2 bb = *reinterpret_cast<const float2*>(&sm[B2S + col]);
                int gi = r0 * SDIM + col;
                float2 xv = *reinterpret_cast<const float2*>(&xT[gi]);
                float2 ev = *reinterpret_cast<const float2*>(&eT[gi]);
                float s0 = ex2f((acc2[nt][0] + bb.x) * 0.72134752044f);
                float s1 = ex2f((acc2[nt][1] + bb.y) * 0.72134752044f);
                float2 o0;
                o0.x = fmaf(s0, ev.x, xv.x);
                o0.y = fmaf(s1, ev.y, xv.y);
                *reinterpret_cast<float2*>(&oT[gi]) = o0;

                int gj = gi + 8 * SDIM;
                float2 xw = *reinterpret_cast<const float2*>(&xT[gj]);
                float2 ew = *reinterpret_cast<const float2*>(&eT[gj]);
                float s2 = ex2f((acc2[nt][2] + bb.x) * 0.72134752044f);
                float s3 = ex2f((acc2[nt][3] + bb.y) * 0.72134752044f);
                float2 o1;
                o1.x = fmaf(s2, ew.x, xw.x);
                o1.y = fmaf(s3, ew.y, xw.y);
                *reinterpret_cast<float2*>(&oT[gj]) = o1;
            }
        }
        __syncthreads();   // protect sH + X slots for next tile
    }
}

extern "C" void kernel_launch(void* const* d_in, const int* in_sizes, int n_in,
                              void* d_out, int out_size) {
    const float* x   = (const float*)d_in[0];
    const float* eps = (const float*)d_in[1];
    const float* W1  = (const float*)d_in[2];
    const float* b1  = (const float*)d_in[3];
    const float* W2  = (const float*)d_in[4];
    const float* b2  = (const float*)d_in[5];
    float* out = (float*)d_out;

    int B = in_sizes[0] / SDIM;
    int numTiles = B / TMR;   // 1024

    static int sms = 0;
    if (!sms) {
        cudaDeviceGetAttribute(&sms, cudaDevAttrMultiProcessorCount, 0);
        cudaFuncSetAttribute(mvn_mma_kernel,
                             cudaFuncAttributeMaxDynamicSharedMemorySize, SMEM_BYTES);
    }
    int grid = sms < numTiles ? sms : numTiles;

    mvn_mma_kernel<<<grid, 256, SMEM_BYTES>>>(x, eps, W1, b1, W2, b2, out, numTiles);
}

// round 5
// speedup vs baseline: 1.6972x; 1.1575x over previous
#include <cuda_runtime.h>
#include <cstdint>

// out = x + exp(0.5*(relu(x@W1+b1)@W2 + b2)) * eps
// x,eps,out [B,256] f32; W1 [256,64]; b1[64]; W2 [64,256]; b2[256]
// Persistent mma.sync (m16n8k8 tf32) kernel, 512 threads/CTA, n-split warp halves.

#define SDIM 256
#define HDIM 64
#define TMR  128
#define NTHREADS 512

// smem float-index offsets
#define W1F 0          // W1 tf32, [k=256][64], XOR-swizzled       (64 KB)
#define W2F 16384      // W2 tf32, [k=64][256], XOR-swizzled       (64 KB)
#define XS0 32768      // X chunk slot0: 128 rows x 64 k, swizzled (32 KB)
#define XS1 40960      // slot1                                    (32 KB)
#define HS  49152      // H tf32: 128 x 64, swizzled               (32 KB)
#define B1S 57344      // 64 f32
#define B2S 57408      // 256 f32
#define SMEM_FLOATS 57664
#define SMEM_BYTES  (SMEM_FLOATS * 4)   // 230656 <= 232448 cap

__device__ __forceinline__ uint32_t to_tf32(float f) {
    uint32_t r; asm("cvt.rna.tf32.f32 %0, %1;" : "=r"(r) : "f"(f)); return r;
}
__device__ __forceinline__ float ex2f(float f) {
    float r; asm("ex2.approx.f32 %0, %1;" : "=f"(r) : "f"(f)); return r;
}
__device__ __forceinline__ void mma8(float* c,
    uint32_t a0, uint32_t a1, uint32_t a2, uint32_t a3, uint32_t b0, uint32_t b1) {
    asm volatile(
        "mma.sync.aligned.m16n8k8.row.col.f32.tf32.tf32.f32 "
        "{%0,%1,%2,%3},{%4,%5,%6,%7},{%8,%9},{%0,%1,%2,%3};"
        : "+f"(c[0]), "+f"(c[1]), "+f"(c[2]), "+f"(c[3])
        : "r"(a0), "r"(a1), "r"(a2), "r"(a3), "r"(b0), "r"(b1));
}

static __device__ __forceinline__ uint32_t smem_u32(const void* p) {
    uint32_t a;
    asm("{ .reg .u64 t; cvta.to.shared.u64 t, %1; cvt.u32.u64 %0, t; }" : "=r"(a) : "l"(p));
    return a;
}
#define CPA16(s, g)  asm volatile("cp.async.cg.shared.global [%0], [%1], 16;" :: "r"(s), "l"(g))
#define CPCOMMIT()   asm volatile("cp.async.commit_group;" ::: "memory")
#define CPWAIT1()    asm volatile("cp.async.wait_group 1;" ::: "memory")

// load one X chunk (128 rows x 64 floats) into a swizzled slot via cp.async
static __device__ __forceinline__ void load_chunk(
    const float* __restrict__ xT, int ck, float* slot) {
    const int tid = threadIdx.x;
    const float* gsrc = xT + ck * 64;
    #pragma unroll
    for (int j = 0; j < 4; j++) {
        int f = tid + NTHREADS * j;
        int m = f >> 4, c4 = f & 15;
        uint32_t dst = smem_u32(slot + m * 64 + 4 * (c4 ^ (m & 7)));
        CPA16(dst, gsrc + m * SDIM + 4 * c4);
    }
}

__global__ void __launch_bounds__(NTHREADS, 1) mvn_mma_kernel(
    const float* __restrict__ x, const float* __restrict__ eps,
    const float* __restrict__ W1, const float* __restrict__ b1,
    const float* __restrict__ W2, const float* __restrict__ b2,
    float* __restrict__ out, int numTiles)
{
    extern __shared__ float sm[];
    uint32_t* smu = reinterpret_cast<uint32_t*>(sm);

    const int tid  = threadIdx.x;
    const int w    = tid >> 5;
    const int wh   = w & 7;       // row group: rows 16*wh .. 16*wh+15
    const int ns   = w >> 3;      // n-split half: 0 or 1
    const int lane = tid & 31;
    const int g    = lane >> 2;
    const int t4   = lane & 3;

    // ---- stage weights (tf32-converted, XOR-swizzled) + biases ----
    #pragma unroll 4
    for (int j = 0; j < 32; j++) {
        int idx = tid + NTHREADS * j;
        int kk = idx >> 6, n = idx & 63;
        smu[W1F + kk * 64 + (n ^ (8 * (kk & 3)))] = to_tf32(W1[idx]);
    }
    #pragma unroll 4
    for (int j = 0; j < 32; j++) {
        int idx = tid + NTHREADS * j;
        int kk = idx >> 8, n = idx & 255;
        smu[W2F + kk * 256 + (n ^ (8 * (kk & 3)))] = to_tf32(W2[idx]);
    }
    if (tid < 64) sm[B1S + tid] = b1[tid];
    if (tid < 256) sm[B2S + tid] = b2[tid];
    __syncthreads();

    const int G = gridDim.x;
    int t = blockIdx.x;

    // prefetch first tile's chunks 0,1
    if (t < numTiles) {
        load_chunk(x + (long long)t * TMR * SDIM, 0, sm + XS0); CPCOMMIT();
        load_chunk(x + (long long)t * TMR * SDIM, 1, sm + XS1); CPCOMMIT();
    }

    const int arow = (16 * wh + g) * 64 + t4;   // A-fragment base (X and H slots)

    for (; t < numTiles; t += G) {
        const long long base = (long long)t * TMR * SDIM;
        const float* xT = x + base;

        // ======== GEMM1 (this warp: H cols 32*ns .. 32*ns+31) ========
        float acc1[4][4];
        #pragma unroll
        for (int nt = 0; nt < 4; nt++)
            acc1[nt][0] = acc1[nt][1] = acc1[nt][2] = acc1[nt][3] = 0.0f;

        #pragma unroll
        for (int c = 0; c < 4; c++) {
            CPWAIT1();
            __syncthreads();
            const float* xs = sm + ((c & 1) ? XS1 : XS0);

            #pragma unroll
            for (int ks = 0; ks < 8; ks++) {
                int a0i = arow + 4 * ((2 * ks) ^ g);
                uint32_t A0 = to_tf32(xs[a0i]);
                uint32_t A1 = to_tf32(xs[a0i + 512]);
                uint32_t A2 = to_tf32(xs[a0i ^ 4]);
                uint32_t A3 = to_tf32(xs[(a0i ^ 4) + 512]);
                const uint32_t* bp = smu + W1F + (64 * c + 8 * ks + t4) * 64 + g + 32 * ns;
                #pragma unroll
                for (int nt = 0; nt < 4; nt++) {
                    int o = 8 * (nt ^ t4);
                    mma8(acc1[nt], A0, A1, A2, A3, bp[o], bp[o + 256]);
                }
            }
            __syncthreads();   // all warps done with this slot

            int tn = t + G;
            if (c == 0)      { load_chunk(xT, 2, sm + XS0); }
            else if (c == 1) { load_chunk(xT, 3, sm + XS1); }
            else if (c == 2) { if (tn < numTiles) load_chunk(x + (long long)tn * TMR * SDIM, 0, sm + XS0); }
            else             { if (tn < numTiles) load_chunk(x + (long long)tn * TMR * SDIM, 1, sm + XS1); }
            CPCOMMIT();   // always commit (possibly empty group) to keep counts uniform
        }

        // ---- bias + relu + store H (tf32 bits) into swizzled smem ----
        {
            const int m0 = (16 * wh + g) * 64;
            #pragma unroll
            for (int nt = 0; nt < 4; nt++) {
                int col = 32 * ns + 8 * nt + 2 * t4;
                float2 bb = *reinterpret_cast<const float2*>(&sm[B1S + col]);
                uint2 p0, p1;
                p0.x = to_tf32(fmaxf(acc1[nt][0] + bb.x, 0.0f));
                p0.y = to_tf32(fmaxf(acc1[nt][1] + bb.y, 0.0f));
                p1.x = to_tf32(fmaxf(acc1[nt][2] + bb.x, 0.0f));
                p1.y = to_tf32(fmaxf(acc1[nt][3] + bb.y, 0.0f));
                int hi = HS + m0 + 4 * ((col >> 2) ^ g) + (col & 3);
                *reinterpret_cast<uint2*>(&smu[hi])       = p0;   // rows g
                *reinterpret_cast<uint2*>(&smu[hi + 512]) = p1;   // rows g+8
            }
        }
        __syncthreads();

        // ======== GEMM2 + fused epilogue (this warp: cc = 2*ns, 2*ns+1) ========
        const float* eT = eps + base;
        float* oT = out + base;
        const int r0 = 16 * wh + g;

        #pragma unroll
        for (int ccl = 0; ccl < 2; ccl++) {
            const int cc = 2 * ns + ccl;
            float acc2[8][4];
            #pragma unroll
            for (int nt = 0; nt < 8; nt++)
                acc2[nt][0] = acc2[nt][1] = acc2[nt][2] = acc2[nt][3] = 0.0f;

            #pragma unroll
            for (int ks = 0; ks < 8; ks++) {
                int a0i = HS + arow + 4 * ((2 * ks) ^ g);
                uint32_t A0 = smu[a0i], A1 = smu[a0i + 512];
                uint32_t A2 = smu[a0i ^ 4], A3 = smu[(a0i ^ 4) + 512];
                const uint32_t* bp = smu + W2F + (8 * ks + t4) * 256 + 64 * cc + g;
                #pragma unroll
                for (int nt = 0; nt < 8; nt++) {
                    int o = 8 * (nt ^ t4);
                    mma8(acc2[nt], A0, A1, A2, A3, bp[o], bp[o + 1024]);
                }
            }

            // epilogue: out = x + exp2(0.72134752*(d + b2)) * eps
            #pragma unroll
            for (int nt = 0; nt < 8; nt++) {
                int col = 64 * cc + 8 * nt + 2 * t4;
                float2 bb = *reinterpret_cast<const float2*>(&sm[B2S + col]);
                int gi = r0 * SDIM + col;
                float2 xv = *reinterpret_cast<const float2*>(&xT[gi]);
                float2 ev = *reinterpret_cast<const float2*>(&eT[gi]);
                float s0 = ex2f((acc2[nt][0] + bb.x) * 0.72134752044f);
                float s1 = ex2f((acc2[nt][1] + bb.y) * 0.72134752044f);
                float2 o0;
                o0.x = fmaf(s0, ev.x, xv.x);
                o0.y = fmaf(s1, ev.y, xv.y);
                *reinterpret_cast<float2*>(&oT[gi]) = o0;

                int gj = gi + 8 * SDIM;
                float2 xw = *reinterpret_cast<const float2*>(&xT[gj]);
                float2 ew = *reinterpret_cast<const float2*>(&eT[gj]);
                float s2 = ex2f((acc2[nt][2] + bb.x) * 0.72134752044f);
                float s3 = ex2f((acc2[nt][3] + bb.y) * 0.72134752044f);
                float2 o1;
                o1.x = fmaf(s2, ew.x, xw.x);
                o1.y = fmaf(s3, ew.y, xw.y);
                *reinterpret_cast<float2*>(&oT[gj]) = o1;
            }
        }
        __syncthreads();   // protect sH + X slots for next tile
    }
}

extern "C" void kernel_launch(void* const* d_in, const int* in_sizes, int n_in,
                              void* d_out, int out_size) {
    const float* x   = (const float*)d_in[0];
    const float* eps = (const float*)d_in[1];
    const float* W1  = (const float*)d_in[2];
    const float* b1  = (const float*)d_in[3];
    const float* W2  = (const float*)d_in[4];
    const float* b2  = (const float*)d_in[5];
    float* out = (float*)d_out;

    int B = in_sizes[0] / SDIM;
    int numTiles = B / TMR;   // 1024

    static int sms = 0;
    if (!sms) {
        cudaDeviceGetAttribute(&sms, cudaDevAttrMultiProcessorCount, 0);
        cudaFuncSetAttribute(mvn_mma_kernel,
                             cudaFuncAttributeMaxDynamicSharedMemorySize, SMEM_BYTES);
    }
    int grid = sms < numTiles ? sms : numTiles;

    mvn_mma_kernel<<<grid, NTHREADS, SMEM_BYTES>>>(x, eps, W1, b1, W2, b2, out, numTiles);
}